// round 3
// baseline (speedup 1.0000x reference)
#include <cuda_runtime.h>
#include <math.h>

#define NMAX 100000
#define EMAX 3200000
#define INC  256
#define HIDC 128
#define OUTC 2

// ---------------- scratch (static device globals; no allocs) ----------------
__device__ __align__(256) float g_deg[NMAX];        // degree, then dinv in-place
__device__ __align__(256) int   g_cnt[NMAX];        // per-dst edge count
__device__ __align__(256) int   g_fill[NMAX];       // CSR fill cursors
__device__ __align__(256) int   g_rowptr[NMAX + 1];
__device__ __align__(256) int   g_bsum[128];        // scan block sums
__device__ __align__(256) int   g_esrc[EMAX];       // CSR: src per slot
__device__ __align__(256) float g_enorm[EMAX];      // CSR: norm per slot
__device__ __align__(256) float g_h [NMAX * HIDC];  // x @ W1
__device__ __align__(256) float g_hr[NMAX * HIDC];  // relu(agg1 + b1)
__device__ __align__(256) float g_t [NMAX * OUTC];  // hr @ W2
__device__ int g_stride2;                           // 1 if edge_index stored as int64

// ---------------- layout detection ----------------
// If edge_index is int64 (little-endian), the high 32-bit word of every entry
// is 0 (all values in [0, 100000)). If it was narrowed to int32, odd words are
// random node ids and the OR is almost surely nonzero.
__global__ void __launch_bounds__(256) k_detect(const int* __restrict__ ei) {
    __shared__ int s_or;
    if (threadIdx.x == 0) s_or = 0;
    __syncthreads();
    int acc = 0;
    for (int i = threadIdx.x; i < 4096; i += 256)
        acc |= ei[2 * i + 1];
    if (acc) atomicOr(&s_or, 1);
    __syncthreads();
    if (threadIdx.x == 0) g_stride2 = (s_or == 0) ? 1 : 0;
}

// ---------------- init ----------------
__global__ void k_init(int n) {
    int i = blockIdx.x * blockDim.x + threadIdx.x;
    if (i < n) {
        g_deg[i]  = 1.0f;   // self-loop weight
        g_cnt[i]  = 0;
        g_fill[i] = 0;
    }
}

// ---------------- edge pass 1: degree + histogram ----------------
__global__ void k_edge1(const int* __restrict__ ei, const float* __restrict__ w,
                        int e, int n) {
    int idx = blockIdx.x * blockDim.x + threadIdx.x;
    if (idx >= e) return;
    int st2 = g_stride2;
    int dst = st2 ? ei[2 * (e + idx)] : ei[e + idx];
    if ((unsigned)dst >= (unsigned)n) return;  // defensive
    atomicAdd(&g_deg[dst], w[idx]);
    atomicAdd(&g_cnt[dst], 1);
}

__global__ void k_dinv(int n) {
    int i = blockIdx.x * blockDim.x + threadIdx.x;
    if (i < n) g_deg[i] = rsqrtf(g_deg[i]);  // deg >= 1 always
}

// ---------------- exclusive scan of g_cnt -> g_rowptr ----------------
__global__ void __launch_bounds__(1024) k_scan1(int n) {
    __shared__ int s[1024];
    int tid = threadIdx.x;
    int i = blockIdx.x * 1024 + tid;
    int v = (i < n) ? g_cnt[i] : 0;
    s[tid] = v;
    __syncthreads();
    for (int off = 1; off < 1024; off <<= 1) {
        int t = (tid >= off) ? s[tid - off] : 0;
        __syncthreads();
        s[tid] += t;
        __syncthreads();
    }
    int incl = s[tid];
    if (i < n) g_rowptr[i] = incl - v;
    if (tid == 1023) g_bsum[blockIdx.x] = incl;
}

__global__ void __launch_bounds__(1024) k_scan2(int nb) {
    __shared__ int s[1024];
    int tid = threadIdx.x;
    int v = (tid < nb) ? g_bsum[tid] : 0;
    s[tid] = v;
    __syncthreads();
    for (int off = 1; off < 1024; off <<= 1) {
        int t = (tid >= off) ? s[tid - off] : 0;
        __syncthreads();
        s[tid] += t;
        __syncthreads();
    }
    if (tid < nb) g_bsum[tid] = s[tid] - v;
}

__global__ void __launch_bounds__(1024) k_scan3(int n, int e) {
    int i = blockIdx.x * 1024 + threadIdx.x;
    if (i < n) g_rowptr[i] += g_bsum[blockIdx.x];
    if (i == 0) g_rowptr[n] = e;
}

// ---------------- edge pass 2: scatter into CSR slots ----------------
__global__ void k_edge2(const int* __restrict__ ei, const float* __restrict__ w,
                        int e, int n) {
    int idx = blockIdx.x * blockDim.x + threadIdx.x;
    if (idx >= e) return;
    int st2 = g_stride2;
    int src = st2 ? ei[2 * idx] : ei[idx];
    int dst = st2 ? ei[2 * (e + idx)] : ei[e + idx];
    if ((unsigned)src >= (unsigned)n || (unsigned)dst >= (unsigned)n) return;
    int pos = g_rowptr[dst] + atomicAdd(&g_fill[dst], 1);
    if ((unsigned)pos >= (unsigned)e) return;  // defensive
    g_esrc[pos]  = src;
    g_enorm[pos] = g_deg[src] * w[idx] * g_deg[dst];
}

// ---------------- GEMM1: h = x @ W1   (n x 256) @ (256 x 128) ----------------
__global__ void __launch_bounds__(256) k_gemm1(const float* __restrict__ x,
                                               const float* __restrict__ W, int n) {
    __shared__ __align__(16) float xs[64][64];
    __shared__ __align__(16) float ws[64][128];
    int tid = threadIdx.x;
    int tr = tid >> 5;
    int tc = tid & 31;
    int row0 = blockIdx.x * 64;

    float4 acc[8];
    #pragma unroll
    for (int r = 0; r < 8; r++) acc[r] = make_float4(0.f, 0.f, 0.f, 0.f);

    for (int kc = 0; kc < 4; kc++) {
        #pragma unroll
        for (int t = 0; t < 4; t++) {
            int f = tid + t * 256;
            int r = f >> 4;
            int kk = (f & 15) * 4;
            int gr = row0 + r;
            float4 v = make_float4(0.f, 0.f, 0.f, 0.f);
            if (gr < n) v = *(const float4*)&x[gr * INC + kc * 64 + kk];
            *(float4*)&xs[r][kk] = v;
        }
        #pragma unroll
        for (int t = 0; t < 8; t++) {
            int f = tid + t * 256;
            int k = f >> 5;
            int c = (f & 31) * 4;
            *(float4*)&ws[k][c] = *(const float4*)&W[(kc * 64 + k) * HIDC + c];
        }
        __syncthreads();

        #pragma unroll 8
        for (int k = 0; k < 64; k++) {
            float4 wv = *(const float4*)&ws[k][tc * 4];
            #pragma unroll
            for (int r = 0; r < 8; r++) {
                float xv = xs[tr * 8 + r][k];
                acc[r].x += xv * wv.x;
                acc[r].y += xv * wv.y;
                acc[r].z += xv * wv.z;
                acc[r].w += xv * wv.w;
            }
        }
        __syncthreads();
    }

    #pragma unroll
    for (int r = 0; r < 8; r++) {
        int gr = row0 + tr * 8 + r;
        if (gr < n) *(float4*)&g_h[gr * HIDC + tc * 4] = acc[r];
    }
}

// ---------------- agg1: warp per node, lane = 4 channels ----------------
__global__ void k_agg1(const float* __restrict__ b1, int n) {
    int warp = (blockIdx.x * blockDim.x + threadIdx.x) >> 5;
    int lane = threadIdx.x & 31;
    if (warp >= n) return;
    const float4* hp = (const float4*)g_h;
    float din = g_deg[warp];
    float sl = din * din;
    float4 hv = hp[warp * 32 + lane];
    float4 acc = make_float4(sl * hv.x, sl * hv.y, sl * hv.z, sl * hv.w);

    int beg = g_rowptr[warp], end = g_rowptr[warp + 1];
    int j = beg;
    for (; j + 1 < end; j += 2) {
        int   s0 = g_esrc[j],     s1 = g_esrc[j + 1];
        float n0 = g_enorm[j],    n1 = g_enorm[j + 1];
        float4 v0 = hp[s0 * 32 + lane];
        float4 v1 = hp[s1 * 32 + lane];
        acc.x += n0 * v0.x + n1 * v1.x;
        acc.y += n0 * v0.y + n1 * v1.y;
        acc.z += n0 * v0.z + n1 * v1.z;
        acc.w += n0 * v0.w + n1 * v1.w;
    }
    if (j < end) {
        int s = g_esrc[j]; float nm = g_enorm[j];
        float4 v = hp[s * 32 + lane];
        acc.x += nm * v.x; acc.y += nm * v.y; acc.z += nm * v.z; acc.w += nm * v.w;
    }

    float b0 = b1[lane * 4 + 0], bb1 = b1[lane * 4 + 1];
    float b2v = b1[lane * 4 + 2], b3 = b1[lane * 4 + 3];
    float4 o;
    o.x = fmaxf(acc.x + b0,  0.f);
    o.y = fmaxf(acc.y + bb1, 0.f);
    o.z = fmaxf(acc.z + b2v, 0.f);
    o.w = fmaxf(acc.w + b3,  0.f);
    ((float4*)g_hr)[warp * 32 + lane] = o;
}

// ---------------- GEMM2: t = hr @ W2  (n x 128) @ (128 x 2) ----------------
__global__ void __launch_bounds__(256) k_gemm2(const float* __restrict__ W2, int n) {
    __shared__ float w2s[HIDC * OUTC];
    if (threadIdx.x < HIDC * OUTC) w2s[threadIdx.x] = W2[threadIdx.x];
    __syncthreads();
    int i = blockIdx.x * blockDim.x + threadIdx.x;
    if (i >= n) return;
    const float4* hr = (const float4*)&g_hr[i * HIDC];
    float ax = 0.f, ay = 0.f;
    #pragma unroll
    for (int k4 = 0; k4 < 32; k4++) {
        float4 v = hr[k4];
        int k = k4 * 4;
        ax += v.x * w2s[(k + 0) * 2] + v.y * w2s[(k + 1) * 2]
            + v.z * w2s[(k + 2) * 2] + v.w * w2s[(k + 3) * 2];
        ay += v.x * w2s[(k + 0) * 2 + 1] + v.y * w2s[(k + 1) * 2 + 1]
            + v.z * w2s[(k + 2) * 2 + 1] + v.w * w2s[(k + 3) * 2 + 1];
    }
    g_t[2 * i]     = ax;
    g_t[2 * i + 1] = ay;
}

// ---------------- agg2: warp per node, lanes stride edges ----------------
__global__ void k_agg2(const float* __restrict__ b2, float* __restrict__ out, int n) {
    int warp = (blockIdx.x * blockDim.x + threadIdx.x) >> 5;
    int lane = threadIdx.x & 31;
    if (warp >= n) return;
    const float2* tp = (const float2*)g_t;
    float ax = 0.f, ay = 0.f;
    int beg = g_rowptr[warp], end = g_rowptr[warp + 1];
    for (int j = beg + lane; j < end; j += 32) {
        int s = g_esrc[j];
        float nm = g_enorm[j];
        float2 v = tp[s];
        ax += nm * v.x;
        ay += nm * v.y;
    }
    #pragma unroll
    for (int off = 16; off; off >>= 1) {
        ax += __shfl_xor_sync(0xffffffffu, ax, off);
        ay += __shfl_xor_sync(0xffffffffu, ay, off);
    }
    if (lane == 0) {
        float din = g_deg[warp];
        float sl = din * din;
        float2 tv = tp[warp];
        out[2 * warp]     = ax + sl * tv.x + b2[0];
        out[2 * warp + 1] = ay + sl * tv.y + b2[1];
    }
}

// ---------------- launcher ----------------
extern "C" void kernel_launch(void* const* d_in, const int* in_sizes, int n_in,
                              void* d_out, int out_size) {
    // Resolve inputs by element count — robust to metadata ordering.
    // x: 25,600,000 | edge_index: 6,400,000 (or 12.8M if counted as int32 words)
    // edge_weight: 3,200,000 | W1: 32,768 | b1: 128 | W2: 256 | b2: 2
    const float* x  = nullptr; const int* ei = nullptr; const float* w  = nullptr;
    const float* W1 = nullptr; const float* b1 = nullptr;
    const float* W2 = nullptr; const float* b2 = nullptr;
    long long e = 0, n = 0;
    for (int i = 0; i < n_in; i++) {
        long long s = in_sizes[i];
        if      (s == 25600000LL) { x  = (const float*)d_in[i]; }
        else if (s == 6400000LL || s == 12800000LL) { ei = (const int*)d_in[i]; }
        else if (s == 3200000LL)  { w  = (const float*)d_in[i]; e = s; }
        else if (s == 32768LL)    { W1 = (const float*)d_in[i]; }
        else if (s == 128LL)      { b1 = (const float*)d_in[i]; }
        else if (s == 256LL)      { W2 = (const float*)d_in[i]; }
        else if (s == 2LL)        { b2 = (const float*)d_in[i]; }
    }
    n = 100000;
    float* out = (float*)d_out;
    int ni = (int)n, ee = (int)e;
    int nb1024 = (ni + 1023) / 1024;

    k_detect<<<1, 256>>>(ei);
    k_init <<<(ni + 255) / 256, 256>>>(ni);
    k_edge1<<<(ee + 255) / 256, 256>>>(ei, w, ee, ni);
    k_dinv <<<(ni + 255) / 256, 256>>>(ni);
    k_scan1<<<nb1024, 1024>>>(ni);
    k_scan2<<<1, 1024>>>(nb1024);
    k_scan3<<<nb1024, 1024>>>(ni, ee);
    k_edge2<<<(ee + 255) / 256, 256>>>(ei, w, ee, ni);
    k_gemm1<<<(ni + 63) / 64, 256>>>(x, W1, ni);
    k_agg1 <<<(ni + 7) / 8, 256>>>(b1, ni);
    k_gemm2<<<(ni + 255) / 256, 256>>>(W2, ni);
    k_agg2 <<<(ni + 7) / 8, 256>>>(b2, out, ni);
}